// round 7
// baseline (speedup 1.0000x reference)
#include <cuda_runtime.h>
#include <math.h>

// ---------------------------------------------------------------------------
// HyperNetworkDecoder: K=2, P=4096, 8 layers of width 64.
// hyper_kernel: generate per-(k,layer) weights once (chunk constant across P),
// stored transposed [m][n].
// decode_kernel: packed-fp32 (fma.rn.f32x2) mainloop. Warp = 16 n-lanes x
// 2 m-halves, 8 points/warp as 4 packed point-pairs; weights in smem,
// x pair-interleaved in smem; LN via packed math + u64 shuffles.
// ---------------------------------------------------------------------------

#define KB 2
typedef unsigned long long u64;

__device__ __align__(16) float g_W0[KB * 128 * 64];      // layer0 W^T [k][m pad128][n]
__device__ __align__(16) float g_Wl[KB * 7 * 64 * 64];   // layers 1..7 W^T [k][l-1][m][n]
__device__ __align__(16) float g_b [KB * 8 * 64];        // biases [k][l][n]

// ---------------------------------------------------------------------------
// Kernel 1: hypernetwork. grid = (k,l) x 16 output-splits = 256 blocks,
// 512 threads: 2 j-groups of 256 handle half the 64-deep reduction each.
// ---------------------------------------------------------------------------
__global__ void __launch_bounds__(512) hyper_kernel(
    const float* __restrict__ latent_tokens,
    const float* __restrict__ token_embeddings,
    const float* __restrict__ h_W0,  const float* __restrict__ h_b0,
    const float* __restrict__ h_ln_s0, const float* __restrict__ h_ln_b0,
    const float* __restrict__ w_W0,  const float* __restrict__ w_b0,
    const float* __restrict__ bb_W0, const float* __restrict__ bb_b0,
    const float* __restrict__ h_W,   const float* __restrict__ h_b,
    const float* __restrict__ h_ln_s, const float* __restrict__ h_ln_b,
    const float* __restrict__ w_W,   const float* __restrict__ w_b,
    const float* __restrict__ bb_W,  const float* __restrict__ bb_b)
{
    __shared__ float chunk[128];
    __shared__ float part[4][64];
    __shared__ float pre[64];
    __shared__ float hbuf[64];
    __shared__ float wpart[1024];

    const int tid = threadIdx.x;
    const int bx  = blockIdx.x;
    const int sp  = bx & 15;
    const int kl  = bx >> 4;
    const int k   = kl >> 3;
    const int l   = kl & 7;

    if (tid < 128)
        chunk[tid] = (tid < 64) ? latent_tokens[(k * 8 + l) * 64 + tid]
                                : token_embeddings[l * 64 + (tid - 64)];
    __syncthreads();

    const float* hWp = (l == 0) ? h_W0 : (h_W + (l - 1) * 128 * 64);
    if (tid < 256) {
        const int q = tid >> 6, j = tid & 63;
        float acc = 0.f;
        #pragma unroll
        for (int i = 0; i < 32; i++) {
            int ii = q * 32 + i;
            acc = fmaf(chunk[ii], __ldg(hWp + ii * 64 + j), acc);
        }
        part[q][j] = acc;
    }
    __syncthreads();
    if (tid < 64) {
        float hb = (l == 0) ? __ldg(h_b0 + tid) : __ldg(h_b + (l - 1) * 64 + tid);
        pre[tid] = part[0][tid] + part[1][tid] + part[2][tid] + part[3][tid] + hb;
    }
    __syncthreads();
    if (tid < 64) {
        float s1 = 0.f, s2 = 0.f;
        #pragma unroll 8
        for (int i = 0; i < 64; i++) { float v = pre[i]; s1 += v; s2 += v * v; }
        float mu   = s1 * (1.f / 64.f);
        float var  = s2 * (1.f / 64.f) - mu * mu;
        float rstd = rsqrtf(var + 1e-6f);
        float ls = (l == 0) ? __ldg(h_ln_s0 + tid) : __ldg(h_ln_s + (l - 1) * 64 + tid);
        float lb = (l == 0) ? __ldg(h_ln_b0 + tid) : __ldg(h_ln_b + (l - 1) * 64 + tid);
        float h  = fmaf((pre[tid] - mu) * rstd, ls, lb);
        hbuf[tid] = fmaxf(h, 0.f);
    }
    __syncthreads();

    const int OUT  = (l == 0) ? 8064 : 4096;
    const int CH   = OUT >> 4;
    const int o0   = sp * CH, oend = o0 + CH;
    const float* wWp = (l == 0) ? w_W0 : (w_W + (l - 1) * 64 * 4096);
    const float* wbp = (l == 0) ? w_b0 : (w_b + (l - 1) * 4096);

    const int g  = tid >> 8;
    const int tt = tid & 255;

    float acc[2];
    #pragma unroll
    for (int i = 0; i < 2; i++) {
        int o = o0 + tt + i * 256;
        acc[i] = (o < oend && g == 0) ? __ldg(wbp + o) : 0.f;
    }
    const int j0 = g * 32;
    #pragma unroll 8
    for (int jj = 0; jj < 32; jj++) {
        float hj = hbuf[j0 + jj];
        const float* row = wWp + (j0 + jj) * OUT;
        #pragma unroll
        for (int i = 0; i < 2; i++) {
            int o = o0 + tt + i * 256;
            if (o < oend) acc[i] = fmaf(hj, __ldg(row + o), acc[i]);
        }
    }
    wpart[g * 512 + tt]       = acc[0];
    wpart[g * 512 + 256 + tt] = acc[1];
    __syncthreads();

    if (g == 0) {
        #pragma unroll
        for (int i = 0; i < 2; i++) {
            int o = o0 + tt + i * 256;
            if (o < oend) {
                float v = acc[i] + wpart[512 + i * 256 + tt];
                if (l == 0) {
                    int n = o / 126, m = o - n * 126;
                    g_W0[k * 8192 + m * 64 + n] = v;
                } else {
                    int n = o >> 6, m = o & 63;
                    g_Wl[k * 28672 + (l - 1) * 4096 + m * 64 + n] = v;
                }
            }
        }
    }

    if (sp == 0) {
        if (l == 0 && tid < 128)
            g_W0[k * 8192 + 8064 + tid] = 0.f;
        if (tid < 64) {
            const float* bWp = (l == 0) ? bb_W0 : (bb_W + (l - 1) * 64 * 64);
            float accb = (l == 0) ? __ldg(bb_b0 + tid) : __ldg(bb_b + (l - 1) * 64 + tid);
            #pragma unroll 8
            for (int j = 0; j < 64; j++)
                accb = fmaf(hbuf[j], __ldg(bWp + j * 64 + tid), accb);
            g_b[(k * 8 + l) * 64 + tid] = accb;
        }
    }
}

// ---------------------------------------------------------------------------
// Packed fp32 (f32x2) primitives — Blackwell sm_100+.
// ---------------------------------------------------------------------------
#define FMA2(D, A, B, C) asm("fma.rn.f32x2 %0, %1, %2, %3;" : "=l"(D) : "l"(A), "l"(B), "l"(C))
#define ADD2(D, A, B)    asm("add.rn.f32x2 %0, %1, %2;"     : "=l"(D) : "l"(A), "l"(B))
#define MUL2(D, A, B)    asm("mul.rn.f32x2 %0, %1, %2;"     : "=l"(D) : "l"(A), "l"(B))

__device__ __forceinline__ u64 pk2(float lo, float hi)
{ u64 d; asm("mov.b64 %0, {%1,%2};" : "=l"(d) : "f"(lo), "f"(hi)); return d; }
__device__ __forceinline__ void upk2(float& lo, float& hi, u64 s)
{ asm("mov.b64 {%0,%1}, %2;" : "=f"(lo), "=f"(hi) : "l"(s)); }

// ---------------------------------------------------------------------------
// Float-only accurate sin: 2-term Cody-Waite reduction by pi, then sinf.
// ---------------------------------------------------------------------------
__device__ __forceinline__ float acc_sin(float x)
{
    float q = rintf(x * 0.318309886183790672f);
    float r = fmaf(-q, 3.14159274101257324f, x);
    r = fmaf(-q, -8.74227800037e-8f, r);
    float s = sinf(r);
    return (((int)q) & 1) ? -s : s;
}

// MM over this thread's m-half for 4 point-pairs.
// Wt: W^T rows of 16 float4 ([m][n0..n0+3] at index m*16+t).
// xw: warp's x region, pair rows of 264 floats (132 float2).
template<int MHALF>
__device__ __forceinline__ void mm2(const float4* __restrict__ Wt,
                                    const float*  __restrict__ xw,
                                    int mbase, int t, u64 acc[16])
{
    #pragma unroll 8
    for (int i = 0; i < MHALF / 2; i++) {
        int m0 = mbase + 2 * i;
        float4 wa = Wt[m0 * 16 + t];
        float4 wb = Wt[m0 * 16 + 16 + t];
        u64 wd0 = pk2(wa.x, wa.x), wd1 = pk2(wa.y, wa.y);
        u64 wd2 = pk2(wa.z, wa.z), wd3 = pk2(wa.w, wa.w);
        u64 we0 = pk2(wb.x, wb.x), we1 = pk2(wb.y, wb.y);
        u64 we2 = pk2(wb.z, wb.z), we3 = pk2(wb.w, wb.w);
        #pragma unroll
        for (int q = 0; q < 4; q++) {
            float4 xv = *(const float4*)(xw + q * 264 + 2 * m0);
            u64 x0 = pk2(xv.x, xv.y);   // (p_even[m0],   p_odd[m0])
            u64 x1 = pk2(xv.z, xv.w);   // (p_even[m0+1], p_odd[m0+1])
            FMA2(acc[q*4+0], x0, wd0, acc[q*4+0]);
            FMA2(acc[q*4+1], x0, wd1, acc[q*4+1]);
            FMA2(acc[q*4+2], x0, wd2, acc[q*4+2]);
            FMA2(acc[q*4+3], x0, wd3, acc[q*4+3]);
            FMA2(acc[q*4+0], x1, we0, acc[q*4+0]);
            FMA2(acc[q*4+1], x1, we1, acc[q*4+1]);
            FMA2(acc[q*4+2], x1, we2, acc[q*4+2]);
            FMA2(acc[q*4+3], x1, we3, acc[q*4+3]);
        }
    }
}

// ---------------------------------------------------------------------------
// Kernel 2: decoder. 128 blocks x 256 threads, 64 points/block (one k).
// Warp wp owns points 8wp..8wp+7 = 4 packed pairs. Lane (t = lane&15,
// h = lane>>4): outputs [4t,4t+4) of all 4 pairs over m-half h.
// ---------------------------------------------------------------------------
__global__ void __launch_bounds__(256, 1) decode_kernel(
    const float* __restrict__ rays,
    const float* __restrict__ ln_s0, const float* __restrict__ ln_b0,
    const float* __restrict__ ln_s,  const float* __restrict__ ln_b,
    const float* __restrict__ rgb_W, const float* __restrict__ rgb_b,
    float* __restrict__ out)
{
    extern __shared__ float smem[];
    float4* sW0 = (float4*)smem;            // 2048 float4  (W0^T 128x64)
    float4* sWl = sW0 + 2048;               // 7168 float4  (7 x 64x64)
    float*  xs  = (float*)(sW0 + 9216);     // 8 warps * 4 pairs * 264 floats

    const int tid  = threadIdx.x;
    const int wp   = tid >> 5;
    const int lane = tid & 31;
    const int t    = lane & 15;
    const int h    = lane >> 4;
    const int n0   = t * 4;
    const int k    = blockIdx.x >> 6;
    const int P0   = 8 * wp;                // first point of this warp

    float* xw = xs + wp * 4 * 264;          // this warp's 4 pair rows

    // ---- weight load (coalesced, 36 float4 per thread) ----
    {
        const float4* s0 = (const float4*)g_W0 + k * 2048;
        const float4* s1 = (const float4*)g_Wl + k * 7168;
        #pragma unroll
        for (int i = 0; i < 8; i++)  sW0[tid + i * 256] = __ldg(s0 + tid + i * 256);
        #pragma unroll
        for (int i = 0; i < 28; i++) sWl[tid + i * 256] = __ldg(s1 + tid + i * 256);
    }

    // ---- positional encoding: 4 lanes per point (pp = lane>>2, s = lane&3) ----
    {
        const int pp = lane >> 2;           // point 0..7 within warp
        const int s  = lane & 3;
        const int q  = pp >> 1, c = pp & 1;
        float* xrow = xw + q * 264;         // float2-interleaved; element m of
                                            // half c at [2m + c]
        const float* r = rays + (blockIdx.x * 64 + P0 + pp) * 6;
        float ox = __ldg(r + 0), oy = __ldg(r + 1), oz = __ldg(r + 2);
        float dx = __ldg(r + 3), dy = __ldg(r + 4), dz = __ldg(r + 5);
        float pl[6];
        pl[0] = dx; pl[1] = dy; pl[2] = dz;
        pl[3] = oy * dz - oz * dy;
        pl[4] = oz * dx - ox * dz;
        pl[5] = ox * dy - oy * dx;
        if (s == 3) {
            #pragma unroll
            for (int cm = 0; cm < 6; cm++) xrow[2 * cm + c] = pl[cm];
            xrow[2 * 126 + c] = 0.f;
            xrow[2 * 127 + c] = 0.f;
        }
        const float PIH = 1.57079632679489662f;
        for (int f = s; f < 10; f += 4) {
            float fr = (float)(1 << f);
            #pragma unroll
            for (int cm = 0; cm < 6; cm++) {
                float a = pl[cm] * fr;
                xrow[2 * (6 + f * 6 + cm) + c]  = acc_sin(a);
                xrow[2 * (66 + f * 6 + cm) + c] = acc_sin(a + PIH);
            }
        }
    }
    __syncthreads();   // the ONLY block barrier

    const float* bb = g_b + k * 512;
    u64 acc[16];

    #pragma unroll 1
    for (int l = 0; l < 8; l++) {
        // init: h==0 carries the bias, h==1 zero (combined after mm)
        float4 b4 = __ldg((const float4*)(bb + l * 64 + n0));
        u64 bi0 = h ? 0ull : pk2(b4.x, b4.x);
        u64 bi1 = h ? 0ull : pk2(b4.y, b4.y);
        u64 bi2 = h ? 0ull : pk2(b4.z, b4.z);
        u64 bi3 = h ? 0ull : pk2(b4.w, b4.w);
        #pragma unroll
        for (int q = 0; q < 4; q++) {
            acc[q*4+0] = bi0; acc[q*4+1] = bi1;
            acc[q*4+2] = bi2; acc[q*4+3] = bi3;
        }

        if (l == 0) mm2<64>(sW0, xw, h * 64, t, acc);
        else        mm2<32>(sWl + (l - 1) * 1024, xw, h * 32, t, acc);

        // combine m-halves (both halves end with full sums)
        #pragma unroll
        for (int a = 0; a < 16; a++) {
            u64 o = __shfl_xor_sync(0xffffffffu, acc[a], 16, 32);
            ADD2(acc[a], acc[a], o);
        }

        const float* lns = (l == 0) ? ln_s0 : (ln_s + (l - 1) * 64);
        const float* lnb = (l == 0) ? ln_b0 : (ln_b + (l - 1) * 64);
        float4 ls4 = __ldg((const float4*)(lns + n0));
        float4 lb4 = __ldg((const float4*)(lnb + n0));
        u64 lsd[4] = { pk2(ls4.x, ls4.x), pk2(ls4.y, ls4.y),
                       pk2(ls4.z, ls4.z), pk2(ls4.w, ls4.w) };
        u64 lbd[4] = { pk2(lb4.x, lb4.x), pk2(lb4.y, lb4.y),
                       pk2(lb4.z, lb4.z), pk2(lb4.w, lb4.w) };

        #pragma unroll
        for (int q = 0; q < 4; q++) {
            u64 s1 = acc[q*4+0];
            ADD2(s1, s1, acc[q*4+1]);
            ADD2(s1, s1, acc[q*4+2]);
            ADD2(s1, s1, acc[q*4+3]);
            u64 s2 = 0ull;
            FMA2(s2, acc[q*4+0], acc[q*4+0], s2);
            FMA2(s2, acc[q*4+1], acc[q*4+1], s2);
            FMA2(s2, acc[q*4+2], acc[q*4+2], s2);
            FMA2(s2, acc[q*4+3], acc[q*4+3], s2);
            #pragma unroll
            for (int m = 1; m < 16; m <<= 1) {
                u64 o1 = __shfl_xor_sync(0xffffffffu, s1, m, 32);
                u64 o2 = __shfl_xor_sync(0xffffffffu, s2, m, 32);
                ADD2(s1, s1, o1);
                ADD2(s2, s2, o2);
            }
            float s1a, s1b, s2a, s2b;
            upk2(s1a, s1b, s1);
            upk2(s2a, s2b, s2);
            float mu0 = s1a * (1.f / 64.f), mu1 = s1b * (1.f / 64.f);
            float rs0 = rsqrtf(s2a * (1.f / 64.f) - mu0 * mu0 + 1e-6f);
            float rs1 = rsqrtf(s2b * (1.f / 64.f) - mu1 * mu1 + 1e-6f);
            u64 nmu = pk2(-mu0, -mu1);
            u64 rsd = pk2(rs0, rs1);
            #pragma unroll
            for (int j = 0; j < 4; j++) {
                u64 tv;
                ADD2(tv, acc[q*4+j], nmu);
                MUL2(tv, tv, rsd);
                FMA2(tv, tv, lsd[j], lbd[j]);
                float f0, f1;
                upk2(f0, f1, tv);
                acc[q*4+j] = pk2(fmaxf(f0, 0.f), fmaxf(f1, 0.f));
            }
        }

        if (l < 7) {
            // store x for next layer: h=0 writes pairs 0,1; h=1 writes 2,3
            #pragma unroll
            for (int qq = 0; qq < 2; qq++) {
                int q = 2 * h + qq;
                ulonglong2 u0; u0.x = acc[q*4+0]; u0.y = acc[q*4+1];
                ulonglong2 u1; u1.x = acc[q*4+2]; u1.y = acc[q*4+3];
                *(ulonglong2*)(xw + q * 264 + 2 * n0)       = u0;
                *(ulonglong2*)(xw + q * 264 + 2 * (n0 + 2)) = u1;
            }
            __syncwarp();
        }
    }

    // ---- rgb head + sigmoid ----
    {
        u64 r2[4][3];
        #pragma unroll
        for (int q = 0; q < 4; q++)
            #pragma unroll
            for (int cc = 0; cc < 3; cc++) r2[q][cc] = 0ull;
        #pragma unroll
        for (int j = 0; j < 4; j++) {
            #pragma unroll
            for (int cc = 0; cc < 3; cc++) {
                float wv = __ldg(rgb_W + (n0 + j) * 3 + cc);
                u64 wd = pk2(wv, wv);
                #pragma unroll
                for (int q = 0; q < 4; q++)
                    FMA2(r2[q][cc], acc[q*4+j], wd, r2[q][cc]);
            }
        }
        #pragma unroll
        for (int m = 1; m < 16; m <<= 1) {
            #pragma unroll
            for (int q = 0; q < 4; q++)
                #pragma unroll
                for (int cc = 0; cc < 3; cc++) {
                    u64 o = __shfl_xor_sync(0xffffffffu, r2[q][cc], m, 32);
                    ADD2(r2[q][cc], r2[q][cc], o);
                }
        }
        if (h == 0 && t < 8) {
            int q = t >> 1, sel = t & 1;
            int gpt = blockIdx.x * 64 + P0 + t;
            #pragma unroll
            for (int cc = 0; cc < 3; cc++) {
                float v0, v1;
                upk2(v0, v1, r2[q][cc]);
                float v = sel ? v1 : v0;
                out[gpt * 3 + cc] = 1.f / (1.f + expf(-(v + __ldg(rgb_b + cc))));
            }
        }
    }
}

// ---------------------------------------------------------------------------
extern "C" void kernel_launch(void* const* d_in, const int* in_sizes, int n_in,
                              void* d_out, int out_size)
{
    const float* rays    = (const float*)d_in[0];
    const float* lat     = (const float*)d_in[1];
    const float* temb    = (const float*)d_in[2];
    const float* h_W0    = (const float*)d_in[3];
    const float* h_b0    = (const float*)d_in[4];
    const float* h_ln_s0 = (const float*)d_in[5];
    const float* h_ln_b0 = (const float*)d_in[6];
    const float* w_W0    = (const float*)d_in[7];
    const float* w_b0    = (const float*)d_in[8];
    const float* bb_W0   = (const float*)d_in[9];
    const float* bb_b0   = (const float*)d_in[10];
    const float* ln_s0   = (const float*)d_in[11];
    const float* ln_b0   = (const float*)d_in[12];
    const float* h_W     = (const float*)d_in[13];
    const float* h_b     = (const float*)d_in[14];
    const float* h_ln_s  = (const float*)d_in[15];
    const float* h_ln_b  = (const float*)d_in[16];
    const float* w_W     = (const float*)d_in[17];
    const float* w_b     = (const float*)d_in[18];
    const float* bb_W    = (const float*)d_in[19];
    const float* bb_b    = (const float*)d_in[20];
    const float* ln_s    = (const float*)d_in[21];
    const float* ln_b    = (const float*)d_in[22];
    const float* rgb_W   = (const float*)d_in[23];
    const float* rgb_b   = (const float*)d_in[24];
    float* out = (float*)d_out;

    // weights 9216*16 = 147456 B, x: 8 warps * 4 pairs * 264 floats = 33792 B
    const int SMEM = 9216 * 16 + 8 * 4 * 264 * 4;   // 181248 B
    cudaFuncSetAttribute(decode_kernel,
                         cudaFuncAttributeMaxDynamicSharedMemorySize, SMEM);

    hyper_kernel<<<256, 512>>>(lat, temb, h_W0, h_b0, h_ln_s0, h_ln_b0,
                               w_W0, w_b0, bb_W0, bb_b0,
                               h_W, h_b, h_ln_s, h_ln_b,
                               w_W, w_b, bb_W, bb_b);
    decode_kernel<<<128, 256, SMEM>>>(rays, ln_s0, ln_b0, ln_s, ln_b,
                                      rgb_W, rgb_b, out);
}